// round 12
// baseline (speedup 1.0000x reference)
#include <cuda_runtime.h>
#include <math.h>

// Problem constants
#define BATCH 8
#define FEAT  64
#define HW    262144             // 512*512
#define NSEG  33                 // ids 0..32 (0 = background)
#define NI    32

// Segment-max config: 128 threads = 4 warps; each warp owns 4 feature planes.
#define THREADS1 128
#define TILEPX   2048            // pixels per work unit
#define NTILE    (HW / TILEPX)   // 128
#define NU       (BATCH * 4 * NTILE)  // 4096 work units (32 bfg x 128 tiles)
#define NB       456             // 152 SMs * 3 CTAs

#define VEC_ELEMS (BATCH * NI * FEAT)   // 16384

// Per-(b,instance,feature) maxima as float bit patterns (nonneg -> int order ok).
// Statically zeroed; mlp kernel re-zeroes after consuming.
__device__ int g_scratch[VEC_ELEMS];
__device__ unsigned int g_cnt[BATCH];   // per-batch arrival tickets (zero-init, self-resetting)

extern __shared__ char smem_raw[];

// ---------------------------------------------------------------------------
// Kernel 1: persistent segment-max, float4 accumulators (4 features/thread).
// s_acc[id*512 + tid*4 + q]: feature f = fg*16 + warp*4 + q, column = tid.
// One LDS.128 + STS.128 updates 4 features per pixel -> ~2x fewer l1tex
// instructions than the scalar loop (the measured limiter).
// ---------------------------------------------------------------------------
__global__ __launch_bounds__(THREADS1, 3)
void segmax_kernel(const float* __restrict__ enc,
                   const int*   __restrict__ masks) {
    float* s_acc = (float*)smem_raw;                          // 33*512 floats = 67584 B
    int*   s_ids = (int*)(smem_raw + NSEG * 512 * 4);         // 2048 ints = 8192 B

    const int tid  = threadIdx.x;
    const int lane = tid & 31;
    const int w    = tid >> 5;          // warp 0..3
    const int k    = blockIdx.x;

    const int s = (k * NU) / NB;
    const int e = ((k + 1) * NU) / NB;

    int cur = -1;
    int b = 0, f0 = 0;                   // f0 = first of this warp's 4 features

    float* accT = s_acc + (tid << 2);    // this thread's float4 column base

    for (int u = s; u < e; ++u) {
        const int bfg = u >> 7;          // u / NTILE
        if (bfg != cur) {
            if (cur >= 0) {
                // flush: each thread's float4 holds 4 features; reduce per id
                #pragma unroll
                for (int id = 1; id < NSEG; ++id) {
                    float4 a = *(const float4*)(accT + (id << 9));
                    #pragma unroll
                    for (int off = 16; off; off >>= 1) {
                        a.x = fmaxf(a.x, __shfl_xor_sync(0xffffffffu, a.x, off));
                        a.y = fmaxf(a.y, __shfl_xor_sync(0xffffffffu, a.y, off));
                        a.z = fmaxf(a.z, __shfl_xor_sync(0xffffffffu, a.z, off));
                        a.w = fmaxf(a.w, __shfl_xor_sync(0xffffffffu, a.w, off));
                    }
                    if (lane == 0) {
                        int* dst = &g_scratch[((b * NI) + (id - 1)) * FEAT + f0];
                        if (a.x > 0.0f) atomicMax(dst + 0, __float_as_int(a.x));
                        if (a.y > 0.0f) atomicMax(dst + 1, __float_as_int(a.y));
                        if (a.z > 0.0f) atomicMax(dst + 2, __float_as_int(a.z));
                        if (a.w > 0.0f) atomicMax(dst + 3, __float_as_int(a.w));
                    }
                }
            }
            #pragma unroll
            for (int r = 0; r < NSEG; ++r)
                *(float4*)(accT + (r << 9)) = make_float4(0.f, 0.f, 0.f, 0.f);
            cur = bfg;
            b  = bfg >> 2;
            f0 = ((bfg & 3) << 4) | (w << 2);
        }
        const int tile = u & (NTILE - 1);

        // Stage mask ids for this tile (premultiplied by 512 = row stride).
        __syncthreads();   // prior tile's s_ids consumers are done
        {
            const int4* mp = (const int4*)(masks + (size_t)b * HW + tile * TILEPX);
            #pragma unroll
            for (int i = tid; i < TILEPX / 4; i += THREADS1) {
                const int4 m = mp[i];
                ((int4*)s_ids)[i] = make_int4(m.x << 9, m.y << 9, m.z << 9, m.w << 9);
            }
        }
        __syncthreads();

        // 4 feature planes for this warp
        const float4* p0 = (const float4*)enc + (size_t)(b * FEAT + f0 + 0) * (HW / 4) + tile * (TILEPX / 4);
        const float4* p1 = (const float4*)enc + (size_t)(b * FEAT + f0 + 1) * (HW / 4) + tile * (TILEPX / 4);
        const float4* p2 = (const float4*)enc + (size_t)(b * FEAT + f0 + 2) * (HW / 4) + tile * (TILEPX / 4);
        const float4* p3 = (const float4*)enc + (size_t)(b * FEAT + f0 + 3) * (HW / 4) + tile * (TILEPX / 4);
        const int4* id4 = (const int4*)s_ids;

        #pragma unroll 2
        for (int g = 0; g < TILEPX / 4 / 32; ++g) {   // 16 iterations
            const int idx = g * 32 + lane;
            const float4 v0 = p0[idx];   // 4 independent LDG.128 streams
            const float4 v1 = p1[idx];
            const float4 v2 = p2[idx];
            const float4 v3 = p3[idx];
            const int4  o = id4[idx];

            {   // pixel 0
                float4 a = *(const float4*)(accT + o.x);
                a.x = fmaxf(a.x, v0.x); a.y = fmaxf(a.y, v1.x);
                a.z = fmaxf(a.z, v2.x); a.w = fmaxf(a.w, v3.x);
                *(float4*)(accT + o.x) = a;
            }
            {   // pixel 1
                float4 a = *(const float4*)(accT + o.y);
                a.x = fmaxf(a.x, v0.y); a.y = fmaxf(a.y, v1.y);
                a.z = fmaxf(a.z, v2.y); a.w = fmaxf(a.w, v3.y);
                *(float4*)(accT + o.y) = a;
            }
            {   // pixel 2
                float4 a = *(const float4*)(accT + o.z);
                a.x = fmaxf(a.x, v0.z); a.y = fmaxf(a.y, v1.z);
                a.z = fmaxf(a.z, v2.z); a.w = fmaxf(a.w, v3.z);
                *(float4*)(accT + o.z) = a;
            }
            {   // pixel 3
                float4 a = *(const float4*)(accT + o.w);
                a.x = fmaxf(a.x, v0.w); a.y = fmaxf(a.y, v1.w);
                a.z = fmaxf(a.z, v2.w); a.w = fmaxf(a.w, v3.w);
                *(float4*)(accT + o.w) = a;
            }
        }
    }

    // final flush
    #pragma unroll
    for (int id = 1; id < NSEG; ++id) {
        float4 a = *(const float4*)(accT + (id << 9));
        #pragma unroll
        for (int off = 16; off; off >>= 1) {
            a.x = fmaxf(a.x, __shfl_xor_sync(0xffffffffu, a.x, off));
            a.y = fmaxf(a.y, __shfl_xor_sync(0xffffffffu, a.y, off));
            a.z = fmaxf(a.z, __shfl_xor_sync(0xffffffffu, a.z, off));
            a.w = fmaxf(a.w, __shfl_xor_sync(0xffffffffu, a.w, off));
        }
        if (lane == 0) {
            int* dst = &g_scratch[((b * NI) + (id - 1)) * FEAT + f0];
            if (a.x > 0.0f) atomicMax(dst + 0, __float_as_int(a.x));
            if (a.y > 0.0f) atomicMax(dst + 1, __float_as_int(a.y));
            if (a.z > 0.0f) atomicMax(dst + 2, __float_as_int(a.z));
            if (a.w > 0.0f) atomicMax(dst + 3, __float_as_int(a.w));
        }
    }

#if __CUDA_ARCH__ >= 900
    cudaTriggerProgrammaticLaunchCompletion();
#endif
}

// ---------------------------------------------------------------------------
// Kernel 2: collapsed relation MLP (R9, unchanged): 152 blocks, PDL.
//   out[b,c,j,i] = sigmoid( v_i.(W1a W2) + v_j.(W1b W2) + (b1 W2 + b2) )
// ---------------------------------------------------------------------------
#define TH2    256
#define SLICES 19
#define OSLICE 216              // ceil(4096 / 19)

__global__ __launch_bounds__(TH2)
void mlp_kernel(const float* __restrict__ w1,
                const float* __restrict__ b1,
                const float* __restrict__ w2,
                const float* __restrict__ b2,
                float* __restrict__ out_vec,
                float* __restrict__ out_conn) {
    __shared__ float s_w1[128 * 32];   // 16 KB
    __shared__ float s_w2[32 * 4];
    __shared__ float s_b1[32];
    __shared__ float s_b2[4];
    __shared__ float s_m1[FEAT * 4];   // (W1a W2)[k][c]
    __shared__ float s_m2[FEAT * 4];   // (W1b W2)[k][c]
    __shared__ float s_c0[4];
    __shared__ float s_v[NI * 65];     // padded stride 65
    __shared__ float s_P[NI * 4];
    __shared__ float s_Q[NI * 4];
    __shared__ unsigned int s_rank;

    const int b   = blockIdx.x / SLICES;
    const int sl  = blockIdx.x % SLICES;
    const int tid = threadIdx.x;

    // ---- PDL prologue: depends ONLY on weight inputs (not on segmax) ----
    #pragma unroll
    for (int t = 0; t < 4; ++t)
        ((float4*)s_w1)[tid + t * TH2] = ((const float4*)w1)[tid + t * TH2];
    if (tid < 32) ((float4*)s_w2)[tid] = ((const float4*)w2)[tid];
    if (tid < 8)  ((float4*)s_b1)[tid] = ((const float4*)b1)[tid];
    if (tid < 4)  s_b2[tid] = b2[tid];
    __syncthreads();

    // fold: m1[k][c] = sum_m w1[k][m] w2[m][c]; m2 likewise for w1[64+k]
    {
        const int kk = tid >> 2, c = tid & 3;
        float a1 = 0.0f, a2 = 0.0f;
        #pragma unroll 8
        for (int m = 0; m < 32; ++m) {
            const float w2v = s_w2[m * 4 + c];
            a1 += s_w1[kk * 32 + m] * w2v;
            a2 += s_w1[(64 + kk) * 32 + m] * w2v;
        }
        s_m1[tid] = a1;
        s_m2[tid] = a2;
        if (tid < 4) {
            float a = s_b2[tid];
            #pragma unroll 8
            for (int m = 0; m < 32; ++m) a += s_b1[m] * s_w2[m * 4 + tid];
            s_c0[tid] = a;
        }
    }

    // ---- wait for segmax's scratch writes to be visible ----
#if __CUDA_ARCH__ >= 900
    cudaGridDependencySynchronize();
#endif

    #pragma unroll
    for (int t = tid; t < NI * FEAT; t += TH2)
        s_v[(t >> 6) * 65 + (t & 63)] = __int_as_float(g_scratch[b * NI * FEAT + t]);
    __syncthreads();

    // P[i][c] = v_i . m1_c ; Q[j][c] = v_j . m2_c
    {
        const int isQ = tid >> 7;
        const int idx = tid & 127;
        const int r = idx >> 2, c = idx & 3;
        const float* vm = s_v + r * 65;
        const float* mm = isQ ? s_m2 : s_m1;
        float a = 0.0f;
        #pragma unroll 8
        for (int kk = 0; kk < FEAT; ++kk) a += vm[kk] * mm[kk * 4 + c];
        if (isQ) s_Q[idx] = a;
        else     s_P[idx] = a;
    }
    __syncthreads();

    // this block's output slice: o in [sl*216, min(4096, sl*216+216))
    {
        const int o = sl * OSLICE + tid;
        if (tid < OSLICE && o < 4096) {      // o = c*1024 + j*32 + i
            const int c = o >> 10;
            const int j = (o >> 5) & 31;
            const int i = o & 31;
            const float t = s_P[i * 4 + c] + s_Q[j * 4 + c] + s_c0[c];
            out_conn[(size_t)b * 4096 + o] = 1.0f / (1.0f + __expf(-t));
        }
    }

    // last block of this batch writes vectors + re-zeroes scratch & ticket.
    __threadfence();
    if (tid == 0) s_rank = atomicAdd(&g_cnt[b], 1u);
    __syncthreads();
    if (s_rank == SLICES - 1) {
        #pragma unroll
        for (int t = tid; t < NI * FEAT; t += TH2) {
            const int gidx = b * NI * FEAT + t;
            out_vec[gidx]   = s_v[(t >> 6) * 65 + (t & 63)];
            g_scratch[gidx] = 0;
        }
        if (tid == 0) g_cnt[b] = 0;
    }
}

// ---------------------------------------------------------------------------
// Launch: segmax, then mlp with programmatic stream serialization (PDL).
// ---------------------------------------------------------------------------
extern "C" void kernel_launch(void* const* d_in, const int* in_sizes, int n_in,
                              void* d_out, int out_size) {
    const float* enc   = (const float*)d_in[0];
    const int*   masks = (const int*)d_in[1];
    const float* w1    = (const float*)d_in[2];
    const float* b1    = (const float*)d_in[3];
    const float* w2    = (const float*)d_in[4];
    const float* b2    = (const float*)d_in[5];

    float* out_vec  = (float*)d_out;
    float* out_conn = out_vec + VEC_ELEMS;

    static bool attr_set = false;
    const int smem_bytes = NSEG * 512 * 4 + TILEPX * 4;  // 75776
    if (!attr_set) {
        cudaFuncSetAttribute(segmax_kernel,
                             cudaFuncAttributeMaxDynamicSharedMemorySize, smem_bytes);
        attr_set = true;
    }

    segmax_kernel<<<NB, THREADS1, smem_bytes>>>(enc, masks);

    cudaLaunchConfig_t cfg = {};
    cfg.gridDim  = dim3(BATCH * SLICES, 1, 1);
    cfg.blockDim = dim3(TH2, 1, 1);
    cfg.dynamicSmemBytes = 0;
    cudaLaunchAttribute attrs[1];
    attrs[0].id = cudaLaunchAttributeProgrammaticStreamSerialization;
    attrs[0].val.programmaticStreamSerializationAllowed = 1;
    cfg.attrs = attrs;
    cfg.numAttrs = 1;
    cudaLaunchKernelEx(&cfg, mlp_kernel, w1, b1, w2, b2, out_vec, out_conn);
}

// round 13
// speedup vs baseline: 1.1290x; 1.1290x over previous
#include <cuda_runtime.h>
#include <math.h>

// Problem constants
#define BATCH 8
#define FEAT  64
#define HW    262144             // 512*512
#define NSEG  33                 // ids 0..32 (0 = background)
#define NI    32

// Segment-max config (R7/R9-proven loop — DO NOT TOUCH)
#define THREADS1 512             // 16 warps = 16 features per (b,fg) group
#define TILEPX   2048            // pixels per work unit
#define NTILE    (HW / TILEPX)   // 128
#define NU       (BATCH * 4 * NTILE)  // 4096 work units
#define NB       456             // 152 SMs * 3 CTAs, exact single wave

#define VEC_ELEMS (BATCH * NI * FEAT)   // 16384

// Per-(b,instance,feature) maxima as float bit patterns (nonneg -> int order ok).
// Statically zeroed; mlp kernel re-zeroes after consuming.
__device__ int g_scratch[VEC_ELEMS];
__device__ unsigned int g_cnt[BATCH];   // per-batch arrival tickets (zero-init, self-resetting)

// Folded MLP weights, computed by fold_kernel each call (same values every
// call -> deterministic): m1 = W1a*W2, m2 = W1b*W2, c0 = b1*W2 + b2.
__device__ float g_m1[FEAT * 4];
__device__ float g_m2[FEAT * 4];
__device__ float g_c0[4];

extern __shared__ char smem_raw[];

// ---------------------------------------------------------------------------
// Kernel 0: weight fold (1 block, ~1.5us; runs before segmax so the mlp's
// critical path after segmax no longer contains cold weight loads or the
// fold stage).
// ---------------------------------------------------------------------------
#define THF 256
__global__ __launch_bounds__(THF)
void fold_kernel(const float* __restrict__ w1,
                 const float* __restrict__ b1,
                 const float* __restrict__ w2,
                 const float* __restrict__ b2) {
    __shared__ float s_w1[128 * 32];   // 16 KB
    __shared__ float s_w2[32 * 4];
    __shared__ float s_b1[32];
    __shared__ float s_b2[4];

    const int tid = threadIdx.x;
    #pragma unroll
    for (int t = 0; t < 4; ++t)
        ((float4*)s_w1)[tid + t * THF] = ((const float4*)w1)[tid + t * THF];
    if (tid < 32) ((float4*)s_w2)[tid] = ((const float4*)w2)[tid];
    if (tid < 8)  ((float4*)s_b1)[tid] = ((const float4*)b1)[tid];
    if (tid < 4)  s_b2[tid] = b2[tid];
    __syncthreads();

    {   // m1[k][c] = sum_m w1[k][m] w2[m][c]; m2 likewise for w1[64+k]
        const int kk = tid >> 2, c = tid & 3;
        float a1 = 0.0f, a2 = 0.0f;
        #pragma unroll 8
        for (int m = 0; m < 32; ++m) {
            const float w2v = s_w2[m * 4 + c];
            a1 += s_w1[kk * 32 + m] * w2v;
            a2 += s_w1[(64 + kk) * 32 + m] * w2v;
        }
        g_m1[tid] = a1;
        g_m2[tid] = a2;
        if (tid < 4) {
            float a = s_b2[tid];
            #pragma unroll 8
            for (int m = 0; m < 32; ++m) a += s_b1[m] * s_w2[m * 4 + tid];
            g_c0[tid] = a;
        }
    }
}

// ---------------------------------------------------------------------------
// Kernel 1: persistent segment-max (R7 structure, byte-identical hot loop).
// ---------------------------------------------------------------------------
__global__ __launch_bounds__(THREADS1, 3)
void segmax_kernel(const float* __restrict__ enc,
                   const int*   __restrict__ masks) {
    float* s_acc = (float*)smem_raw;                          // 33*512 floats = 67584 B
    int*   s_ids = (int*)(smem_raw + NSEG * THREADS1 * 4);    // 2048 ints   =  8192 B

    const int tid  = threadIdx.x;
    const int lane = tid & 31;
    const int w    = tid >> 5;
    const int k    = blockIdx.x;

    const int s = (k * NU) / NB;
    const int e = ((k + 1) * NU) / NB;

    int cur = -1;
    int b = 0, f = 0;

    for (int u = s; u < e; ++u) {
        const int bfg = u >> 7;             // u / NTILE
        if (bfg != cur) {
            if (cur >= 0) {
                // flush: column tid is private to this thread; warp-reduce per id
                #pragma unroll
                for (int id = 1; id < NSEG; ++id) {
                    float v = s_acc[(id << 9) + tid];
                    #pragma unroll
                    for (int off = 16; off; off >>= 1)
                        v = fmaxf(v, __shfl_xor_sync(0xffffffffu, v, off));
                    if (lane == 0 && v > 0.0f)
                        atomicMax(&g_scratch[((b * NI) + (id - 1)) * FEAT + f],
                                  __float_as_int(v));
                }
            }
            #pragma unroll
            for (int r = 0; r < NSEG; ++r) s_acc[(r << 9) + tid] = 0.0f;
            cur = bfg;
            b = bfg >> 2;
            f = ((bfg & 3) << 4) | w;
        }
        const int tile = u & (NTILE - 1);

        // Stage mask ids for this tile (premultiplied by 512 = row stride).
        __syncthreads();   // prior tile's s_ids consumers are done
        {
            const int4 m = ((const int4*)(masks + (size_t)b * HW + tile * TILEPX))[tid];
            ((int4*)s_ids)[tid] = make_int4(m.x << 9, m.y << 9, m.z << 9, m.w << 9);
        }
        __syncthreads();

        const float4* src4 = (const float4*)enc
                           + (size_t)(b * FEAT + f) * (HW / 4)
                           + tile * (TILEPX / 4);
        const int4* id4 = (const int4*)s_ids;

        #pragma unroll 4
        for (int g = 0; g < TILEPX / 4 / 32; ++g) {   // 16 iterations
            const int idx = g * 32 + lane;
            const float4 v = src4[idx];
            const int4  o = id4[idx];
            float a;
            a = s_acc[o.x + tid]; if (v.x > a) s_acc[o.x + tid] = v.x;
            a = s_acc[o.y + tid]; if (v.y > a) s_acc[o.y + tid] = v.y;
            a = s_acc[o.z + tid]; if (v.z > a) s_acc[o.z + tid] = v.z;
            a = s_acc[o.w + tid]; if (v.w > a) s_acc[o.w + tid] = v.w;
        }
    }

    // final flush
    #pragma unroll
    for (int id = 1; id < NSEG; ++id) {
        float v = s_acc[(id << 9) + tid];
        #pragma unroll
        for (int off = 16; off; off >>= 1)
            v = fmaxf(v, __shfl_xor_sync(0xffffffffu, v, off));
        if (lane == 0 && v > 0.0f)
            atomicMax(&g_scratch[((b * NI) + (id - 1)) * FEAT + f],
                      __float_as_int(v));
    }

#if __CUDA_ARCH__ >= 900
    cudaTriggerProgrammaticLaunchCompletion();
#endif
}

// ---------------------------------------------------------------------------
// Kernel 2: relation MLP final stage (fold precomputed):
//   out[b,c,j,i] = sigmoid( P[i][c] + Q[j][c] + c0[c] ),
//   P[i] = v_i . m1,  Q[j] = v_j . m2.
// 152 blocks (19 per batch), PDL; m1/m2/c0 staged pre-sync (L2-hot).
// ---------------------------------------------------------------------------
#define TH2    256
#define SLICES 19
#define OSLICE 216              // ceil(4096 / 19)

__global__ __launch_bounds__(TH2)
void mlp_kernel(float* __restrict__ out_vec,
                float* __restrict__ out_conn) {
    __shared__ float s_m1[FEAT * 4];
    __shared__ float s_m2[FEAT * 4];
    __shared__ float s_c0[4];
    __shared__ float s_v[NI * 65];     // padded stride 65
    __shared__ float s_P[NI * 4];
    __shared__ float s_Q[NI * 4];
    __shared__ unsigned int s_rank;

    const int b   = blockIdx.x / SLICES;
    const int sl  = blockIdx.x % SLICES;
    const int tid = threadIdx.x;

    // ---- prologue (pre-sync): folded weights, written by fold_kernel which
    // completed before segmax even started -> safe to read before the sync ----
    s_m1[tid] = g_m1[tid];
    s_m2[tid] = g_m2[tid];
    if (tid < 4) s_c0[tid] = g_c0[tid];

    // ---- wait for segmax's scratch writes to be visible ----
#if __CUDA_ARCH__ >= 900
    cudaGridDependencySynchronize();
#endif

    #pragma unroll
    for (int t = tid; t < NI * FEAT; t += TH2)
        s_v[(t >> 6) * 65 + (t & 63)] = __int_as_float(g_scratch[b * NI * FEAT + t]);
    __syncthreads();

    // P[i][c] = v_i . m1_c ; Q[j][c] = v_j . m2_c  (4-way split accumulators)
    {
        const int isQ = tid >> 7;
        const int idx = tid & 127;
        const int r = idx >> 2, c = idx & 3;
        const float* vm = s_v + r * 65;
        const float* mm = (isQ ? s_m2 : s_m1) + c;
        float a0 = 0.f, a1 = 0.f, a2 = 0.f, a3 = 0.f;
        #pragma unroll
        for (int kk = 0; kk < FEAT; kk += 4) {
            a0 += vm[kk + 0] * mm[(kk + 0) * 4];
            a1 += vm[kk + 1] * mm[(kk + 1) * 4];
            a2 += vm[kk + 2] * mm[(kk + 2) * 4];
            a3 += vm[kk + 3] * mm[(kk + 3) * 4];
        }
        const float a = (a0 + a1) + (a2 + a3);
        if (isQ) s_Q[idx] = a;
        else     s_P[idx] = a;
    }
    __syncthreads();

    // this block's output slice: o in [sl*216, min(4096, sl*216+216))
    {
        const int o = sl * OSLICE + tid;
        if (tid < OSLICE && o < 4096) {      // o = c*1024 + j*32 + i
            const int c = o >> 10;
            const int j = (o >> 5) & 31;
            const int i = o & 31;
            const float t = s_P[i * 4 + c] + s_Q[j * 4 + c] + s_c0[c];
            out_conn[(size_t)b * 4096 + o] = 1.0f / (1.0f + __expf(-t));
        }
    }

    // last block of this batch writes vectors + re-zeroes scratch & ticket.
    __threadfence();
    if (tid == 0) s_rank = atomicAdd(&g_cnt[b], 1u);
    __syncthreads();
    if (s_rank == SLICES - 1) {
        #pragma unroll
        for (int t = tid; t < NI * FEAT; t += TH2) {
            const int gidx = b * NI * FEAT + t;
            out_vec[gidx]   = s_v[(t >> 6) * 65 + (t & 63)];
            g_scratch[gidx] = 0;
        }
        if (tid == 0) g_cnt[b] = 0;
    }
}

// ---------------------------------------------------------------------------
// Launch: fold -> segmax -> mlp (mlp with PDL).
// ---------------------------------------------------------------------------
extern "C" void kernel_launch(void* const* d_in, const int* in_sizes, int n_in,
                              void* d_out, int out_size) {
    const float* enc   = (const float*)d_in[0];
    const int*   masks = (const int*)d_in[1];
    const float* w1    = (const float*)d_in[2];
    const float* b1    = (const float*)d_in[3];
    const float* w2    = (const float*)d_in[4];
    const float* b2    = (const float*)d_in[5];

    float* out_vec  = (float*)d_out;
    float* out_conn = out_vec + VEC_ELEMS;

    static bool attr_set = false;
    const int smem_bytes = NSEG * THREADS1 * 4 + TILEPX * 4;  // 75776
    if (!attr_set) {
        cudaFuncSetAttribute(segmax_kernel,
                             cudaFuncAttributeMaxDynamicSharedMemorySize, smem_bytes);
        attr_set = true;
    }

    fold_kernel<<<1, THF>>>(w1, b1, w2, b2);

    segmax_kernel<<<NB, THREADS1, smem_bytes>>>(enc, masks);

    cudaLaunchConfig_t cfg = {};
    cfg.gridDim  = dim3(BATCH * SLICES, 1, 1);
    cfg.blockDim = dim3(TH2, 1, 1);
    cfg.dynamicSmemBytes = 0;
    cudaLaunchAttribute attrs[1];
    attrs[0].id = cudaLaunchAttributeProgrammaticStreamSerialization;
    attrs[0].val.programmaticStreamSerializationAllowed = 1;
    cfg.attrs = attrs;
    cfg.numAttrs = 1;
    cudaLaunchKernelEx(&cfg, mlp_kernel, out_vec, out_conn);
}